// round 4
// baseline (speedup 1.0000x reference)
#include <cuda_runtime.h>

// GraphLearning: hidden_cat = feat @ (att ⊙ W_lin) + b_lin  (single 512x512 GEMM)
//                a_l/a_r fused in GEMM epilogue; factors via L2-resident float4 gather.
// R2 fix: src/dst are int32 (JAX x64 disabled silently demotes int64 -> int32).
//         Indices additionally clamped so a dtype surprise shows as rel_err, not IMA.

#define NMAX 100000
#define D_IN 512
#define GDIM 4
#define HDIM 128

__device__ float  g_Wcat[GDIM * D_IN * HDIM];   // [g][d][h], 1 MB
__device__ float4 g_al[NMAX];                   // a_l per node, g-contiguous
__device__ float4 g_ar[NMAX];

// ---------------- prep: fold att into W_lin ----------------
__global__ void prep_kernel(const float* __restrict__ att,
                            const float* __restrict__ Wlin) {
    int i = blockIdx.x * blockDim.x + threadIdx.x;
    if (i < GDIM * D_IN * HDIM) {
        int g = i >> 16;            // / (512*128)
        int d = (i >> 7) & 511;     // / 128 % 512
        g_Wcat[i] = att[g * D_IN + d] * Wlin[i];
    }
}

// ---------------- packed f32x2 helpers ----------------
__device__ __forceinline__ unsigned long long pack2(float lo, float hi) {
    unsigned long long r;
    asm("mov.b64 %0, {%1, %2};" : "=l"(r) : "f"(lo), "f"(hi));
    return r;
}
__device__ __forceinline__ void fma2(unsigned long long& d,
                                     unsigned long long a,
                                     unsigned long long b) {
    asm("fma.rn.f32x2 %0, %1, %2, %0;" : "+l"(d) : "l"(a), "l"(b));
}
__device__ __forceinline__ float2 unpack2(unsigned long long v) {
    float2 r;
    asm("mov.b64 {%0, %1}, %2;" : "=f"(r.x), "=f"(r.y) : "l"(v));
    return r;
}

// ---------------- GEMM + epilogue ----------------
// grid: (4, ceil(N/128)); block: (16,16). Each block: 128 rows x 128 cols (one g group).
// Micro-tile: 8x8 per thread, accumulated as 8 rows x 4 col-pairs of f32x2.
#define BM 128
#define BK 16
#define AS_STRIDE 132   // pad: keeps float4 alignment, breaks bank conflicts

__global__ __launch_bounds__(256, 2)
void gemm_kernel(const float* __restrict__ feat,
                 const float* __restrict__ b_lin,
                 const float* __restrict__ w_al, const float* __restrict__ b_al,
                 const float* __restrict__ w_ar, const float* __restrict__ b_ar,
                 float* __restrict__ out_hidden, int N) {
    __shared__ float As[BK][AS_STRIDE];   // [k][m]
    __shared__ float Bs[BK][HDIM];        // [k][n]

    const int g    = blockIdx.x;
    const int row0 = blockIdx.y * BM;
    const int tx = threadIdx.x, ty = threadIdx.y;
    const int tid = ty * 16 + tx;
    const float* Bmat = g_Wcat + g * (D_IN * HDIM);

    unsigned long long acc[8][4];
#pragma unroll
    for (int r = 0; r < 8; r++)
#pragma unroll
        for (int p = 0; p < 4; p++) acc[r][p] = 0ull;

    for (int k0 = 0; k0 < D_IN; k0 += BK) {
        // A tile: 128 rows x 16 k, transposed into As[k][m]
#pragma unroll
        for (int i = 0; i < 2; i++) {
            int idx = tid + i * 256;
            int m = idx >> 2, kq = (idx & 3) << 2;
            float4 v = make_float4(0.f, 0.f, 0.f, 0.f);
            int row = row0 + m;
            if (row < N)
                v = *reinterpret_cast<const float4*>(feat + (size_t)row * D_IN + k0 + kq);
            As[kq + 0][m] = v.x; As[kq + 1][m] = v.y;
            As[kq + 2][m] = v.z; As[kq + 3][m] = v.w;
        }
        // B tile: 16 k x 128 cols, natural layout
#pragma unroll
        for (int i = 0; i < 2; i++) {
            int idx = tid + i * 256;
            int kk = idx >> 5, c = (idx & 31) << 2;
            *reinterpret_cast<float4*>(&Bs[kk][c]) =
                *reinterpret_cast<const float4*>(Bmat + (size_t)(k0 + kk) * HDIM + c);
        }
        __syncthreads();

#pragma unroll
        for (int kk = 0; kk < BK; kk++) {
            float4 a0 = *reinterpret_cast<const float4*>(&As[kk][ty * 8]);
            float4 a1 = *reinterpret_cast<const float4*>(&As[kk][ty * 8 + 4]);
            // B pairs read directly as packed 64-bit lanes (no movs needed)
            ulonglong2 bq0 = *reinterpret_cast<const ulonglong2*>(&Bs[kk][tx * 8]);
            ulonglong2 bq1 = *reinterpret_cast<const ulonglong2*>(&Bs[kk][tx * 8 + 4]);
            unsigned long long bp[4] = {bq0.x, bq0.y, bq1.x, bq1.y};
            float a[8] = {a0.x, a0.y, a0.z, a0.w, a1.x, a1.y, a1.z, a1.w};
#pragma unroll
            for (int r = 0; r < 8; r++) {
                unsigned long long av = pack2(a[r], a[r]);
#pragma unroll
                for (int p = 0; p < 4; p++) fma2(acc[r][p], av, bp[p]);
            }
        }
        __syncthreads();
    }

    // Epilogue: +bias, store hidden, fused a_l/a_r row dots
    const float* bl  = b_lin + g * HDIM;
    const float* wal = w_al + g * HDIM;
    const float* war = w_ar + g * HDIM;

#pragma unroll
    for (int r = 0; r < 8; r++) {
        int row = row0 + ty * 8 + r;
        float h[8];
#pragma unroll
        for (int p = 0; p < 4; p++) {
            float2 v = unpack2(acc[r][p]);
            h[2 * p] = v.x; h[2 * p + 1] = v.y;
        }
        float la = 0.f, ra = 0.f;
#pragma unroll
        for (int c = 0; c < 8; c++) {
            int col = tx * 8 + c;
            h[c] += bl[col];
            la += h[c] * wal[col];
            ra += h[c] * war[col];
        }
        if (row < N) {
            float* dst = out_hidden + (size_t)row * (GDIM * HDIM) + g * HDIM + tx * 8;
            *reinterpret_cast<float4*>(dst)     = make_float4(h[0], h[1], h[2], h[3]);
            *reinterpret_cast<float4*>(dst + 4) = make_float4(h[4], h[5], h[6], h[7]);
        }
        // reduce across the 16 tx lanes (each holds 8 of the 128 cols)
#pragma unroll
        for (int s = 8; s > 0; s >>= 1) {
            la += __shfl_xor_sync(0xffffffffu, la, s, 16);
            ra += __shfl_xor_sync(0xffffffffu, ra, s, 16);
        }
        if (tx == 0 && row < N) {
            reinterpret_cast<float*>(g_al)[row * 4 + g] = la + b_al[g];
            reinterpret_cast<float*>(g_ar)[row * 4 + g] = ra + b_ar[g];
        }
    }
}

// ---------------- edge factors ----------------
// src/dst are int32 (JAX default x64-disabled demotes the requested int64).
// Clamp defensively: a wrong-dtype surprise then shows up as rel_err, not an IMA.
__global__ void edge_kernel(const int* __restrict__ src,
                            const int* __restrict__ dst,
                            float* __restrict__ factors, int E, int N) {
    size_t stride = (size_t)gridDim.x * blockDim.x;
    for (size_t e = (size_t)blockIdx.x * blockDim.x + threadIdx.x; e < (size_t)E; e += stride) {
        int s = src[e]; s = s < 0 ? 0 : (s >= N ? N - 1 : s);
        int d = dst[e]; d = d < 0 ? 0 : (d >= N ? N - 1 : d);
        float4 l = g_al[s];
        float4 r = g_ar[d];
        factors[e]                 = 1.f / (1.f + __expf(-(l.x + r.x)));
        factors[(size_t)E + e]     = 1.f / (1.f + __expf(-(l.y + r.y)));
        factors[(size_t)2 * E + e] = 1.f / (1.f + __expf(-(l.z + r.z)));
        factors[(size_t)3 * E + e] = 1.f / (1.f + __expf(-(l.w + r.w)));
    }
}

// ---------------- launch ----------------
extern "C" void kernel_launch(void* const* d_in, const int* in_sizes, int n_in,
                              void* d_out, int out_size) {
    const float* feat  = (const float*)d_in[0];
    const int*   src   = (const int*)d_in[1];
    const int*   dst   = (const int*)d_in[2];
    const float* att   = (const float*)d_in[3];
    const float* Wlin  = (const float*)d_in[4];
    const float* b_lin = (const float*)d_in[5];
    const float* w_al  = (const float*)d_in[6];
    const float* b_al  = (const float*)d_in[7];
    const float* w_ar  = (const float*)d_in[8];
    const float* b_ar  = (const float*)d_in[9];

    int N = in_sizes[0] / D_IN;
    int E = in_sizes[1];
    float* out     = (float*)d_out;
    float* factors = out + (size_t)N * (GDIM * HDIM);

    prep_kernel<<<(GDIM * D_IN * HDIM + 255) / 256, 256>>>(att, Wlin);

    dim3 grid(GDIM, (N + BM - 1) / BM);   // g fastest -> 4 g-blocks of same rows share feat via L2
    gemm_kernel<<<grid, dim3(16, 16)>>>(feat, b_lin, w_al, b_al, w_ar, b_ar, out, N);

    edge_kernel<<<2048, 256>>>(src, dst, factors, E, N);
}

// round 6
// speedup vs baseline: 1.8685x; 1.8685x over previous
#include <cuda_runtime.h>
#include <cuda_bf16.h>
#include <cstdint>

// GraphLearning via mma.sync bf16x3 (tcgen05 unavailable: harness targets sm_103, not sm_103a).
// hidden_cat = feat @ B, B[d, g*128+h] = att[g,d]*Wlin[g,d,h]
// 3-term compensated bf16 MMA: Ahi*Bhi + Ahi*Blo + Alo*Bhi  -> rel_err ~1e-5.
// a_l/a_r fused in epilogue; factors via L2-resident float4 gather (int32 indices).

#define NMAX   100000
#define D_IN   512
#define GDIM   4
#define HDIM   128
#define BM     128
#define BN     128
#define KC     32
#define NIT    (D_IN / KC)      // 16
#define ASTR   40               // smem row stride in bf16 elems (80 B) -> conflict-free ldmatrix

// B pre-transposed [g][n][k], bf16 hi/lo (1 MB each, L2-resident)
__device__ __nv_bfloat16 g_Bhi[GDIM * HDIM * D_IN];
__device__ __nv_bfloat16 g_Blo[GDIM * HDIM * D_IN];
__device__ float4 g_al[NMAX];
__device__ float4 g_ar[NMAX];

// ---------------- helpers ----------------
__device__ __forceinline__ uint32_t smem_u32(const void* p) {
    uint32_t a;
    asm("{ .reg .u64 t; cvta.to.shared.u64 t, %1; cvt.u32.u64 %0, t; }" : "=r"(a) : "l"(p));
    return a;
}
__device__ __forceinline__ void ldsm4(uint32_t& r0, uint32_t& r1, uint32_t& r2, uint32_t& r3,
                                      uint32_t addr) {
    asm volatile("ldmatrix.sync.aligned.m8n8.x4.shared.b16 {%0,%1,%2,%3}, [%4];"
                 : "=r"(r0), "=r"(r1), "=r"(r2), "=r"(r3) : "r"(addr));
}
__device__ __forceinline__ void mma16816(float* c, const uint32_t* a, uint32_t b0, uint32_t b1) {
    asm volatile("mma.sync.aligned.m16n8k16.row.col.f32.bf16.bf16.f32 "
                 "{%0,%1,%2,%3}, {%4,%5,%6,%7}, {%8,%9}, {%0,%1,%2,%3};"
                 : "+f"(c[0]), "+f"(c[1]), "+f"(c[2]), "+f"(c[3])
                 : "r"(a[0]), "r"(a[1]), "r"(a[2]), "r"(a[3]), "r"(b0), "r"(b1));
}
__device__ __forceinline__ uint32_t pack_bf2(__nv_bfloat16 a, __nv_bfloat16 b) {
    __nv_bfloat162 t; t.x = a; t.y = b;
    return *reinterpret_cast<uint32_t*>(&t);
}

// ---------------- prep: fold att, split hi/lo, transpose to [n][k] ----------------
__global__ void prep_kernel(const float* __restrict__ att,
                            const float* __restrict__ Wlin) {
    int i = blockIdx.x * blockDim.x + threadIdx.x;    // [g][d][h] flat
    if (i >= GDIM * D_IN * HDIM) return;
    int g = i >> 16, d = (i >> 7) & 511, n = i & 127;
    float w = att[g * D_IN + d] * Wlin[i];
    __nv_bfloat16 hi = __float2bfloat16_rn(w);
    __nv_bfloat16 lo = __float2bfloat16_rn(w - __bfloat162float(hi));
    size_t idx = (size_t)g * (HDIM * D_IN) + (size_t)n * D_IN + d;
    g_Bhi[idx] = hi;
    g_Blo[idx] = lo;
}

// ---------------- GEMM: 512 thr, 4x4 warps, warp tile m32n32 ----------------
// smem: A_hi | A_lo | B_hi | B_lo, each 128 rows x 40 elems x 2B = 10240 B
#define SM_AH 0
#define SM_AL 10240
#define SM_BH 20480
#define SM_BL 30720
#define SM_SZ 40960

__global__ __launch_bounds__(512, 1)
void gemm_kernel(const float* __restrict__ feat,
                 const float* __restrict__ b_lin,
                 const float* __restrict__ w_al, const float* __restrict__ b_al,
                 const float* __restrict__ w_ar, const float* __restrict__ b_ar,
                 float* __restrict__ out_hidden, int N) {
    __shared__ __align__(16) char sm[SM_SZ];
    const uint32_t sb = smem_u32(sm);

    const int tid = threadIdx.x, wid = tid >> 5, lid = tid & 31;
    const int wm = wid & 3, wn = wid >> 2;          // warp grid 4(m) x 4(n)
    const int g = blockIdx.x;
    const int row0 = blockIdx.y * BM;

    // loader: thread -> (row, 8-elem k chunk)
    const int lrow = tid >> 2;
    const int lkq  = (tid & 3) * 8;
    const bool rowok = (row0 + lrow) < N;
    const float* abase = feat + (size_t)(row0 + lrow) * D_IN + lkq;
    const __nv_bfloat16* bh_base = g_Bhi + (size_t)g * (HDIM * D_IN) + (size_t)lrow * D_IN + lkq;
    const __nv_bfloat16* bl_base = g_Blo + (size_t)g * (HDIM * D_IN) + (size_t)lrow * D_IN + lkq;
    const uint32_t sts_off = (uint32_t)lrow * (ASTR * 2) + (uint32_t)(tid & 3) * 16;

    // prefetch chunk 0
    float4 pa0 = make_float4(0.f, 0.f, 0.f, 0.f), pa1 = pa0;
    if (rowok) {
        pa0 = *reinterpret_cast<const float4*>(abase);
        pa1 = *reinterpret_cast<const float4*>(abase + 4);
    }
    uint4 pbh = *reinterpret_cast<const uint4*>(bh_base);
    uint4 pbl = *reinterpret_cast<const uint4*>(bl_base);

    float c[2][4][4];
#pragma unroll
    for (int mi = 0; mi < 2; mi++)
#pragma unroll
        for (int ni = 0; ni < 4; ni++)
#pragma unroll
            for (int j = 0; j < 4; j++) c[mi][ni][j] = 0.f;

    // ldmatrix address components (same pattern for A and B tiles)
    const uint32_t lrs  = (uint32_t)(lid & 15);     // row select
    const uint32_t lkh  = (uint32_t)(lid >> 4);     // k half (16B)

    for (int it = 0; it < NIT; it++) {
        if (it) __syncthreads();
        // ---- STS: convert A fp32 -> bf16 hi/lo; copy B ----
        {
            __nv_bfloat16 h0 = __float2bfloat16_rn(pa0.x), h1 = __float2bfloat16_rn(pa0.y);
            __nv_bfloat16 h2 = __float2bfloat16_rn(pa0.z), h3 = __float2bfloat16_rn(pa0.w);
            __nv_bfloat16 h4 = __float2bfloat16_rn(pa1.x), h5 = __float2bfloat16_rn(pa1.y);
            __nv_bfloat16 h6 = __float2bfloat16_rn(pa1.z), h7 = __float2bfloat16_rn(pa1.w);
            uint4 hv = make_uint4(pack_bf2(h0, h1), pack_bf2(h2, h3),
                                  pack_bf2(h4, h5), pack_bf2(h6, h7));
            uint4 lv = make_uint4(
                pack_bf2(__float2bfloat16_rn(pa0.x - __bfloat162float(h0)),
                         __float2bfloat16_rn(pa0.y - __bfloat162float(h1))),
                pack_bf2(__float2bfloat16_rn(pa0.z - __bfloat162float(h2)),
                         __float2bfloat16_rn(pa0.w - __bfloat162float(h3))),
                pack_bf2(__float2bfloat16_rn(pa1.x - __bfloat162float(h4)),
                         __float2bfloat16_rn(pa1.y - __bfloat162float(h5))),
                pack_bf2(__float2bfloat16_rn(pa1.z - __bfloat162float(h6)),
                         __float2bfloat16_rn(pa1.w - __bfloat162float(h7))));
            *reinterpret_cast<uint4*>(sm + SM_AH + sts_off) = hv;
            *reinterpret_cast<uint4*>(sm + SM_AL + sts_off) = lv;
            *reinterpret_cast<uint4*>(sm + SM_BH + sts_off) = pbh;
            *reinterpret_cast<uint4*>(sm + SM_BL + sts_off) = pbl;
        }
        __syncthreads();
        // ---- prefetch next chunk (overlaps HMMA below) ----
        if (it + 1 < NIT) {
            int ko = (it + 1) * KC;
            if (rowok) {
                pa0 = *reinterpret_cast<const float4*>(abase + ko);
                pa1 = *reinterpret_cast<const float4*>(abase + ko + 4);
            }
            pbh = *reinterpret_cast<const uint4*>(bh_base + ko);
            pbl = *reinterpret_cast<const uint4*>(bl_base + ko);
        }
        // ---- compute: 2 ksteps of 16 ----
#pragma unroll
        for (int ks = 0; ks < 2; ks++) {
            const uint32_t koff = (uint32_t)ks * 32 + lkh * 16;
            uint32_t aH[2][4], aL[2][4];
#pragma unroll
            for (int mi = 0; mi < 2; mi++) {
                uint32_t ra = (uint32_t)(wm * 32 + mi * 16) + lrs;
                ldsm4(aH[mi][0], aH[mi][1], aH[mi][2], aH[mi][3],
                      sb + SM_AH + ra * (ASTR * 2) + koff);
                ldsm4(aL[mi][0], aL[mi][1], aL[mi][2], aL[mi][3],
                      sb + SM_AL + ra * (ASTR * 2) + koff);
            }
            uint32_t bH[4][2], bL[4][2];
#pragma unroll
            for (int p = 0; p < 2; p++) {
                uint32_t rb = (uint32_t)(wn * 32 + p * 16) + lrs;
                uint32_t r0, r1, r2, r3;
                ldsm4(r0, r1, r2, r3, sb + SM_BH + rb * (ASTR * 2) + koff);
                bH[2 * p][0] = r0; bH[2 * p][1] = r2;
                bH[2 * p + 1][0] = r1; bH[2 * p + 1][1] = r3;
                ldsm4(r0, r1, r2, r3, sb + SM_BL + rb * (ASTR * 2) + koff);
                bL[2 * p][0] = r0; bL[2 * p][1] = r2;
                bL[2 * p + 1][0] = r1; bL[2 * p + 1][1] = r3;
            }
#pragma unroll
            for (int mi = 0; mi < 2; mi++)
#pragma unroll
                for (int ni = 0; ni < 4; ni++) {
                    mma16816(c[mi][ni], aH[mi], bH[ni][0], bH[ni][1]);
                    mma16816(c[mi][ni], aH[mi], bL[ni][0], bL[ni][1]);
                    mma16816(c[mi][ni], aL[mi], bH[ni][0], bH[ni][1]);
                }
        }
    }

    // ---------------- epilogue ----------------
    __syncthreads();                    // all LDSM done; reuse smem for reductions
    float* laR = reinterpret_cast<float*>(sm);            // [4][128]
    float* raR = reinterpret_cast<float*>(sm + 2048);

    const int quad = lid >> 2, tq = lid & 3;
    const float* bl  = b_lin + g * HDIM;
    const float* wal = w_al + g * HDIM;
    const float* war = w_ar + g * HDIM;

#pragma unroll
    for (int mi = 0; mi < 2; mi++)
#pragma unroll
        for (int h = 0; h < 2; h++) {
            int rl = wm * 32 + mi * 16 + h * 8 + quad;
            int rg = row0 + rl;
            bool ok = rg < N;
            float la = 0.f, ra = 0.f;
            float* dst = out_hidden + (size_t)rg * (GDIM * HDIM) + g * HDIM;
#pragma unroll
            for (int ni = 0; ni < 4; ni++) {
                int col = wn * 32 + ni * 8 + tq * 2;
                float v0 = c[mi][ni][h * 2 + 0] + __ldg(bl + col);
                float v1 = c[mi][ni][h * 2 + 1] + __ldg(bl + col + 1);
                la += v0 * __ldg(wal + col) + v1 * __ldg(wal + col + 1);
                ra += v0 * __ldg(war + col) + v1 * __ldg(war + col + 1);
                if (ok) *reinterpret_cast<float2*>(dst + col) = make_float2(v0, v1);
            }
            la += __shfl_xor_sync(0xffffffffu, la, 1);
            la += __shfl_xor_sync(0xffffffffu, la, 2);
            ra += __shfl_xor_sync(0xffffffffu, ra, 1);
            ra += __shfl_xor_sync(0xffffffffu, ra, 2);
            if (tq == 0) { laR[wn * 128 + rl] = la; raR[wn * 128 + rl] = ra; }
        }
    __syncthreads();
    if (tid < 128) {
        int rg = row0 + tid;
        if (rg < N) {
            float la = laR[tid] + laR[128 + tid] + laR[256 + tid] + laR[384 + tid];
            float ra = raR[tid] + raR[128 + tid] + raR[256 + tid] + raR[384 + tid];
            reinterpret_cast<float*>(g_al)[rg * 4 + g] = la + b_al[g];
            reinterpret_cast<float*>(g_ar)[rg * 4 + g] = ra + b_ar[g];
        }
    }
}

// ---------------- edge factors ----------------
__global__ void edge_kernel(const int* __restrict__ src,
                            const int* __restrict__ dst,
                            float* __restrict__ factors, int E, int N) {
    size_t stride = (size_t)gridDim.x * blockDim.x;
    for (size_t e = (size_t)blockIdx.x * blockDim.x + threadIdx.x; e < (size_t)E; e += stride) {
        int s = src[e]; s = s < 0 ? 0 : (s >= N ? N - 1 : s);
        int d = dst[e]; d = d < 0 ? 0 : (d >= N ? N - 1 : d);
        float4 l = g_al[s];
        float4 r = g_ar[d];
        factors[e]                 = 1.f / (1.f + __expf(-(l.x + r.x)));
        factors[(size_t)E + e]     = 1.f / (1.f + __expf(-(l.y + r.y)));
        factors[(size_t)2 * E + e] = 1.f / (1.f + __expf(-(l.z + r.z)));
        factors[(size_t)3 * E + e] = 1.f / (1.f + __expf(-(l.w + r.w)));
    }
}

// ---------------- launch ----------------
extern "C" void kernel_launch(void* const* d_in, const int* in_sizes, int n_in,
                              void* d_out, int out_size) {
    const float* feat  = (const float*)d_in[0];
    const int*   src   = (const int*)d_in[1];
    const int*   dst   = (const int*)d_in[2];
    const float* att   = (const float*)d_in[3];
    const float* Wlin  = (const float*)d_in[4];
    const float* b_lin = (const float*)d_in[5];
    const float* w_al  = (const float*)d_in[6];
    const float* b_al  = (const float*)d_in[7];
    const float* w_ar  = (const float*)d_in[8];
    const float* b_ar  = (const float*)d_in[9];

    int N = in_sizes[0] / D_IN;
    int E = in_sizes[1];
    float* out     = (float*)d_out;
    float* factors = out + (size_t)N * (GDIM * HDIM);

    prep_kernel<<<(GDIM * D_IN * HDIM + 255) / 256, 256>>>(att, Wlin);

    dim3 grid(GDIM, (N + BM - 1) / BM);   // g fastest: 4 CTAs share each feat tile via L2
    gemm_kernel<<<grid, 512>>>(feat, b_lin, w_al, b_al, w_ar, b_ar, out, N);

    edge_kernel<<<2048, 256>>>(src, dst, factors, E, N);
}

// round 7
// speedup vs baseline: 2.7244x; 1.4581x over previous
#include <cuda_runtime.h>
#include <cuda_fp16.h>
#include <cstdint>

// GraphLearning via mma.sync fp16 2-term compensation (A split hi/lo fp16 -> A exact to 2^-22;
// B single fp16 -> rel_err ~1.4e-4, dominated by B rounding). Double-buffered smem pipeline.
// hidden_cat = feat @ B, B[d, g*128+h] = att[g,d]*Wlin[g,d,h]
// a_l/a_r fused in epilogue; factors via L2-resident float4 gather (int32 indices).

#define NMAX   100000
#define D_IN   512
#define GDIM   4
#define HDIM   128
#define BM     128
#define KC     32
#define NIT    (D_IN / KC)      // 16
#define ASTR   40               // smem row stride in fp16 elems (80 B) -> conflict-free ldmatrix

// B pre-transposed [g][n][k], fp16 (1 MB, L2-resident)
__device__ __half g_Bh[GDIM * HDIM * D_IN];
__device__ float4 g_al[NMAX];
__device__ float4 g_ar[NMAX];

// ---------------- helpers ----------------
__device__ __forceinline__ uint32_t smem_u32(const void* p) {
    uint32_t a;
    asm("{ .reg .u64 t; cvta.to.shared.u64 t, %1; cvt.u32.u64 %0, t; }" : "=r"(a) : "l"(p));
    return a;
}
__device__ __forceinline__ void ldsm4(uint32_t& r0, uint32_t& r1, uint32_t& r2, uint32_t& r3,
                                      uint32_t addr) {
    asm volatile("ldmatrix.sync.aligned.m8n8.x4.shared.b16 {%0,%1,%2,%3}, [%4];"
                 : "=r"(r0), "=r"(r1), "=r"(r2), "=r"(r3) : "r"(addr));
}
__device__ __forceinline__ void mma16816(float* c, const uint32_t* a, uint32_t b0, uint32_t b1) {
    asm volatile("mma.sync.aligned.m16n8k16.row.col.f32.f16.f16.f32 "
                 "{%0,%1,%2,%3}, {%4,%5,%6,%7}, {%8,%9}, {%0,%1,%2,%3};"
                 : "+f"(c[0]), "+f"(c[1]), "+f"(c[2]), "+f"(c[3])
                 : "r"(a[0]), "r"(a[1]), "r"(a[2]), "r"(a[3]), "r"(b0), "r"(b1));
}
__device__ __forceinline__ uint32_t pack_h2(__half a, __half b) {
    __half2 t; t.x = a; t.y = b;
    return *reinterpret_cast<uint32_t*>(&t);
}

// ---------------- prep: fold att, fp16 round, transpose to [n][k] ----------------
__global__ void prep_kernel(const float* __restrict__ att,
                            const float* __restrict__ Wlin) {
    int i = blockIdx.x * blockDim.x + threadIdx.x;    // [g][d][h] flat
    if (i >= GDIM * D_IN * HDIM) return;
    int g = i >> 16, d = (i >> 7) & 511, n = i & 127;
    float w = att[g * D_IN + d] * Wlin[i];
    g_Bh[(size_t)g * (HDIM * D_IN) + (size_t)n * D_IN + d] = __float2half_rn(w);
}

// ---------------- GEMM: 512 thr, 4x4 warps, warp tile m32n32, double-buffered ----------------
// per-buffer smem: A_hi | A_lo | B_h, each 128 x 40 fp16 = 10240 B; two buffers = 61440 B
#define T_AH 0
#define T_AL 10240
#define T_BH 20480
#define BUF_SZ 30720
#define SM_SZ  (2 * BUF_SZ)

__global__ __launch_bounds__(512, 1)
void gemm_kernel(const float* __restrict__ feat,
                 const float* __restrict__ b_lin,
                 const float* __restrict__ w_al, const float* __restrict__ b_al,
                 const float* __restrict__ w_ar, const float* __restrict__ b_ar,
                 float* __restrict__ out_hidden, int N) {
    extern __shared__ __align__(16) char sm[];
    const uint32_t sb = smem_u32(sm);

    const int tid = threadIdx.x, wid = tid >> 5, lid = tid & 31;
    const int wm = wid & 3, wn = wid >> 2;          // warp grid 4(m) x 4(n)
    const int g = blockIdx.x;
    const int row0 = blockIdx.y * BM;

    // loader: thread -> (row, 8-elem k chunk)
    const int lrow = tid >> 2;
    const bool rowok = (row0 + lrow) < N;
    const float* abase = feat + (size_t)(row0 + lrow) * D_IN + (tid & 3) * 8;
    const __half* bbase = g_Bh + (size_t)g * (HDIM * D_IN) + (size_t)lrow * D_IN + (tid & 3) * 8;
    const uint32_t sts_off = (uint32_t)lrow * (ASTR * 2) + (uint32_t)(tid & 3) * 16;

    // prefetch chunk 0
    float4 pa0 = make_float4(0.f, 0.f, 0.f, 0.f), pa1 = pa0;
    if (rowok) {
        pa0 = *reinterpret_cast<const float4*>(abase);
        pa1 = *reinterpret_cast<const float4*>(abase + 4);
    }
    uint4 pbh = *reinterpret_cast<const uint4*>(bbase);

    float c[2][4][4];
#pragma unroll
    for (int mi = 0; mi < 2; mi++)
#pragma unroll
        for (int ni = 0; ni < 4; ni++)
#pragma unroll
            for (int j = 0; j < 4; j++) c[mi][ni][j] = 0.f;

    const uint32_t lrs = (uint32_t)(lid & 15);      // ldmatrix row select
    const uint32_t lkh = (uint32_t)(lid >> 4);      // k half (16B)

    // STS of a prefetched chunk into buffer `base`
    auto sts_chunk = [&](uint32_t base) {
        __half h0 = __float2half_rn(pa0.x), h1 = __float2half_rn(pa0.y);
        __half h2 = __float2half_rn(pa0.z), h3 = __float2half_rn(pa0.w);
        __half h4 = __float2half_rn(pa1.x), h5 = __float2half_rn(pa1.y);
        __half h6 = __float2half_rn(pa1.z), h7 = __float2half_rn(pa1.w);
        uint4 hv = make_uint4(pack_h2(h0, h1), pack_h2(h2, h3),
                              pack_h2(h4, h5), pack_h2(h6, h7));
        uint4 lv = make_uint4(
            pack_h2(__float2half_rn(pa0.x - __half2float(h0)),
                    __float2half_rn(pa0.y - __half2float(h1))),
            pack_h2(__float2half_rn(pa0.z - __half2float(h2)),
                    __float2half_rn(pa0.w - __half2float(h3))),
            pack_h2(__float2half_rn(pa1.x - __half2float(h4)),
                    __float2half_rn(pa1.y - __half2float(h5))),
            pack_h2(__float2half_rn(pa1.z - __half2float(h6)),
                    __float2half_rn(pa1.w - __half2float(h7))));
        *reinterpret_cast<uint4*>(sm + base + T_AH + sts_off) = hv;
        *reinterpret_cast<uint4*>(sm + base + T_AL + sts_off) = lv;
        *reinterpret_cast<uint4*>(sm + base + T_BH + sts_off) = pbh;
    };

    sts_chunk(0);
    __syncthreads();

    for (int it = 0; it < NIT; it++) {
        const uint32_t cur = (uint32_t)(it & 1) * BUF_SZ;
        // ---- prefetch next chunk (LDG latency hidden under MMA block) ----
        if (it + 1 < NIT) {
            int ko = (it + 1) * KC;
            if (rowok) {
                pa0 = *reinterpret_cast<const float4*>(abase + ko);
                pa1 = *reinterpret_cast<const float4*>(abase + ko + 4);
            }
            pbh = *reinterpret_cast<const uint4*>(bbase + ko);
        }
        // ---- compute on buffer `cur`: 2 ksteps of 16 ----
#pragma unroll
        for (int ks = 0; ks < 2; ks++) {
            const uint32_t koff = (uint32_t)ks * 32 + lkh * 16;
            uint32_t aH[2][4], aL[2][4];
#pragma unroll
            for (int mi = 0; mi < 2; mi++) {
                uint32_t ra = (uint32_t)(wm * 32 + mi * 16) + lrs;
                ldsm4(aH[mi][0], aH[mi][1], aH[mi][2], aH[mi][3],
                      sb + cur + T_AH + ra * (ASTR * 2) + koff);
                ldsm4(aL[mi][0], aL[mi][1], aL[mi][2], aL[mi][3],
                      sb + cur + T_AL + ra * (ASTR * 2) + koff);
            }
            uint32_t bB[4][2];
#pragma unroll
            for (int p = 0; p < 2; p++) {
                uint32_t rb = (uint32_t)(wn * 32 + p * 16) + lrs;
                uint32_t r0, r1, r2, r3;
                ldsm4(r0, r1, r2, r3, sb + cur + T_BH + rb * (ASTR * 2) + koff);
                bB[2 * p][0] = r0; bB[2 * p][1] = r2;
                bB[2 * p + 1][0] = r1; bB[2 * p + 1][1] = r3;
            }
#pragma unroll
            for (int mi = 0; mi < 2; mi++)
#pragma unroll
                for (int ni = 0; ni < 4; ni++) {
                    mma16816(c[mi][ni], aH[mi], bB[ni][0], bB[ni][1]);
                    mma16816(c[mi][ni], aL[mi], bB[ni][0], bB[ni][1]);
                }
        }
        // ---- stage next chunk into the other buffer; one sync per iter ----
        if (it + 1 < NIT) {
            sts_chunk(cur ^ BUF_SZ);
            __syncthreads();
        }
    }

    // ---------------- epilogue ----------------
    __syncthreads();                    // all LDSM done; reuse smem for reductions
    float* laR = reinterpret_cast<float*>(sm);            // [4][128]
    float* raR = reinterpret_cast<float*>(sm + 2048);

    const int quad = lid >> 2, tq = lid & 3;
    const float* bl  = b_lin + g * HDIM;
    const float* wal = w_al + g * HDIM;
    const float* war = w_ar + g * HDIM;

#pragma unroll
    for (int mi = 0; mi < 2; mi++)
#pragma unroll
        for (int h = 0; h < 2; h++) {
            int rl = wm * 32 + mi * 16 + h * 8 + quad;
            int rg = row0 + rl;
            bool ok = rg < N;
            float la = 0.f, ra = 0.f;
            float* dst = out_hidden + (size_t)rg * (GDIM * HDIM) + g * HDIM;
#pragma unroll
            for (int ni = 0; ni < 4; ni++) {
                int col = wn * 32 + ni * 8 + tq * 2;
                float v0 = c[mi][ni][h * 2 + 0] + __ldg(bl + col);
                float v1 = c[mi][ni][h * 2 + 1] + __ldg(bl + col + 1);
                la += v0 * __ldg(wal + col) + v1 * __ldg(wal + col + 1);
                ra += v0 * __ldg(war + col) + v1 * __ldg(war + col + 1);
                if (ok) *reinterpret_cast<float2*>(dst + col) = make_float2(v0, v1);
            }
            la += __shfl_xor_sync(0xffffffffu, la, 1);
            la += __shfl_xor_sync(0xffffffffu, la, 2);
            ra += __shfl_xor_sync(0xffffffffu, ra, 1);
            ra += __shfl_xor_sync(0xffffffffu, ra, 2);
            if (tq == 0) { laR[wn * 128 + rl] = la; raR[wn * 128 + rl] = ra; }
        }
    __syncthreads();
    if (tid < 128) {
        int rg = row0 + tid;
        if (rg < N) {
            float la = laR[tid] + laR[128 + tid] + laR[256 + tid] + laR[384 + tid];
            float ra = raR[tid] + raR[128 + tid] + raR[256 + tid] + raR[384 + tid];
            reinterpret_cast<float*>(g_al)[rg * 4 + g] = la + b_al[g];
            reinterpret_cast<float*>(g_ar)[rg * 4 + g] = ra + b_ar[g];
        }
    }
}

// ---------------- edge factors ----------------
__global__ void edge_kernel(const int* __restrict__ src,
                            const int* __restrict__ dst,
                            float* __restrict__ factors, int E, int N) {
    size_t stride = (size_t)gridDim.x * blockDim.x;
    for (size_t e = (size_t)blockIdx.x * blockDim.x + threadIdx.x; e < (size_t)E; e += stride) {
        int s = src[e]; s = s < 0 ? 0 : (s >= N ? N - 1 : s);
        int d = dst[e]; d = d < 0 ? 0 : (d >= N ? N - 1 : d);
        float4 l = g_al[s];
        float4 r = g_ar[d];
        factors[e]                 = 1.f / (1.f + __expf(-(l.x + r.x)));
        factors[(size_t)E + e]     = 1.f / (1.f + __expf(-(l.y + r.y)));
        factors[(size_t)2 * E + e] = 1.f / (1.f + __expf(-(l.z + r.z)));
        factors[(size_t)3 * E + e] = 1.f / (1.f + __expf(-(l.w + r.w)));
    }
}

// ---------------- launch ----------------
extern "C" void kernel_launch(void* const* d_in, const int* in_sizes, int n_in,
                              void* d_out, int out_size) {
    const float* feat  = (const float*)d_in[0];
    const int*   src   = (const int*)d_in[1];
    const int*   dst   = (const int*)d_in[2];
    const float* att   = (const float*)d_in[3];
    const float* Wlin  = (const float*)d_in[4];
    const float* b_lin = (const float*)d_in[5];
    const float* w_al  = (const float*)d_in[6];
    const float* b_al  = (const float*)d_in[7];
    const float* w_ar  = (const float*)d_in[8];
    const float* b_ar  = (const float*)d_in[9];

    int N = in_sizes[0] / D_IN;
    int E = in_sizes[1];
    float* out     = (float*)d_out;
    float* factors = out + (size_t)N * (GDIM * HDIM);

    cudaFuncSetAttribute(gemm_kernel, cudaFuncAttributeMaxDynamicSharedMemorySize, SM_SZ);

    prep_kernel<<<(GDIM * D_IN * HDIM + 255) / 256, 256>>>(att, Wlin);

    dim3 grid(GDIM, (N + BM - 1) / BM);   // g fastest: 4 CTAs share each feat tile via L2
    gemm_kernel<<<grid, 512, SM_SZ>>>(feat, b_lin, w_al, b_al, w_ar, b_ar, out, N);

    edge_kernel<<<2048, 256>>>(src, dst, factors, E, N);
}

// round 8
// speedup vs baseline: 2.8953x; 1.0627x over previous
#include <cuda_runtime.h>
#include <cuda_fp16.h>
#include <cstdint>

// GraphLearning via mma.sync fp16 single-term (A fp16, B fp16, fp32 accum).
// Measured R7: HMMA issue-bound at ~16 cyc/SMSP -> halving MMA count is the only lever.
// Error: A+B fp16 rounding ~ sqrt(2) * 2.08e-4 ~ 2.9e-4 << 1e-3 gate.
// hidden_cat = feat @ B, B[d, g*128+h] = att[g,d]*Wlin[g,d,h]
// a_l/a_r fused in epilogue; factors via L2-resident float4 gather (int32 indices).

#define NMAX   100000
#define D_IN   512
#define GDIM   4
#define HDIM   128
#define BM     128
#define KC     32
#define NIT    (D_IN / KC)      // 16
#define ASTR   40               // smem row stride in fp16 elems (80 B) -> conflict-free ldmatrix

// B pre-transposed [g][n][k], fp16 (1 MB, L2-resident)
__device__ __half g_Bh[GDIM * HDIM * D_IN];
__device__ float4 g_al[NMAX];
__device__ float4 g_ar[NMAX];

// ---------------- helpers ----------------
__device__ __forceinline__ uint32_t smem_u32(const void* p) {
    uint32_t a;
    asm("{ .reg .u64 t; cvta.to.shared.u64 t, %1; cvt.u32.u64 %0, t; }" : "=r"(a) : "l"(p));
    return a;
}
__device__ __forceinline__ void ldsm4(uint32_t& r0, uint32_t& r1, uint32_t& r2, uint32_t& r3,
                                      uint32_t addr) {
    asm volatile("ldmatrix.sync.aligned.m8n8.x4.shared.b16 {%0,%1,%2,%3}, [%4];"
                 : "=r"(r0), "=r"(r1), "=r"(r2), "=r"(r3) : "r"(addr));
}
__device__ __forceinline__ void mma16816(float* c, const uint32_t* a, uint32_t b0, uint32_t b1) {
    asm volatile("mma.sync.aligned.m16n8k16.row.col.f32.f16.f16.f32 "
                 "{%0,%1,%2,%3}, {%4,%5,%6,%7}, {%8,%9}, {%0,%1,%2,%3};"
                 : "+f"(c[0]), "+f"(c[1]), "+f"(c[2]), "+f"(c[3])
                 : "r"(a[0]), "r"(a[1]), "r"(a[2]), "r"(a[3]), "r"(b0), "r"(b1));
}
__device__ __forceinline__ uint32_t pack_h2(__half a, __half b) {
    __half2 t; t.x = a; t.y = b;
    return *reinterpret_cast<uint32_t*>(&t);
}

// ---------------- prep: fold att, fp16 round, transpose to [n][k] ----------------
__global__ void prep_kernel(const float* __restrict__ att,
                            const float* __restrict__ Wlin) {
    int i = blockIdx.x * blockDim.x + threadIdx.x;    // [g][d][h] flat
    if (i >= GDIM * D_IN * HDIM) return;
    int g = i >> 16, d = (i >> 7) & 511, n = i & 127;
    float w = att[g * D_IN + d] * Wlin[i];
    g_Bh[(size_t)g * (HDIM * D_IN) + (size_t)n * D_IN + d] = __float2half_rn(w);
}

// ---------------- GEMM: 512 thr, 4x4 warps, warp tile m32n32, double-buffered ----------------
// per-buffer smem: A | B, each 128 x 40 fp16 = 10240 B; two buffers = 40960 B
#define T_A  0
#define T_B  10240
#define BUF_SZ 20480
#define SM_SZ  (2 * BUF_SZ)

__global__ __launch_bounds__(512, 1)
void gemm_kernel(const float* __restrict__ feat,
                 const float* __restrict__ b_lin,
                 const float* __restrict__ w_al, const float* __restrict__ b_al,
                 const float* __restrict__ w_ar, const float* __restrict__ b_ar,
                 float* __restrict__ out_hidden, int N) {
    extern __shared__ __align__(16) char sm[];
    const uint32_t sb = smem_u32(sm);

    const int tid = threadIdx.x, wid = tid >> 5, lid = tid & 31;
    const int wm = wid & 3, wn = wid >> 2;          // warp grid 4(m) x 4(n)
    const int g = blockIdx.x;
    const int row0 = blockIdx.y * BM;

    // loader: thread -> (row, 8-elem k chunk)
    const int lrow = tid >> 2;
    const bool rowok = (row0 + lrow) < N;
    const float* abase = feat + (size_t)(row0 + lrow) * D_IN + (tid & 3) * 8;
    const __half* bbase = g_Bh + (size_t)g * (HDIM * D_IN) + (size_t)lrow * D_IN + (tid & 3) * 8;
    const uint32_t sts_off = (uint32_t)lrow * (ASTR * 2) + (uint32_t)(tid & 3) * 16;

    // prefetch chunk 0
    float4 pa0 = make_float4(0.f, 0.f, 0.f, 0.f), pa1 = pa0;
    if (rowok) {
        pa0 = *reinterpret_cast<const float4*>(abase);
        pa1 = *reinterpret_cast<const float4*>(abase + 4);
    }
    uint4 pbh = *reinterpret_cast<const uint4*>(bbase);

    float c[2][4][4];
#pragma unroll
    for (int mi = 0; mi < 2; mi++)
#pragma unroll
        for (int ni = 0; ni < 4; ni++)
#pragma unroll
            for (int j = 0; j < 4; j++) c[mi][ni][j] = 0.f;

    const uint32_t lrs = (uint32_t)(lid & 15);      // ldmatrix row select
    const uint32_t lkh = (uint32_t)(lid >> 4);      // k half (16B)

    // STS of the prefetched chunk into buffer `base`
    auto sts_chunk = [&](uint32_t base) {
        uint4 hv = make_uint4(
            pack_h2(__float2half_rn(pa0.x), __float2half_rn(pa0.y)),
            pack_h2(__float2half_rn(pa0.z), __float2half_rn(pa0.w)),
            pack_h2(__float2half_rn(pa1.x), __float2half_rn(pa1.y)),
            pack_h2(__float2half_rn(pa1.z), __float2half_rn(pa1.w)));
        *reinterpret_cast<uint4*>(sm + base + T_A + sts_off) = hv;
        *reinterpret_cast<uint4*>(sm + base + T_B + sts_off) = pbh;
    };

    sts_chunk(0);
    __syncthreads();

    for (int it = 0; it < NIT; it++) {
        const uint32_t cur = (uint32_t)(it & 1) * BUF_SZ;
        // ---- prefetch next chunk (LDG latency hidden under MMA block) ----
        if (it + 1 < NIT) {
            int ko = (it + 1) * KC;
            if (rowok) {
                pa0 = *reinterpret_cast<const float4*>(abase + ko);
                pa1 = *reinterpret_cast<const float4*>(abase + ko + 4);
            }
            pbh = *reinterpret_cast<const uint4*>(bbase + ko);
        }
        // ---- compute on buffer `cur`: 2 ksteps of 16 ----
#pragma unroll
        for (int ks = 0; ks < 2; ks++) {
            const uint32_t koff = (uint32_t)ks * 32 + lkh * 16;
            uint32_t aA[2][4];
#pragma unroll
            for (int mi = 0; mi < 2; mi++) {
                uint32_t ra = (uint32_t)(wm * 32 + mi * 16) + lrs;
                ldsm4(aA[mi][0], aA[mi][1], aA[mi][2], aA[mi][3],
                      sb + cur + T_A + ra * (ASTR * 2) + koff);
            }
            uint32_t bB[4][2];
#pragma unroll
            for (int p = 0; p < 2; p++) {
                uint32_t rb = (uint32_t)(wn * 32 + p * 16) + lrs;
                uint32_t r0, r1, r2, r3;
                ldsm4(r0, r1, r2, r3, sb + cur + T_B + rb * (ASTR * 2) + koff);
                bB[2 * p][0] = r0; bB[2 * p][1] = r2;
                bB[2 * p + 1][0] = r1; bB[2 * p + 1][1] = r3;
            }
#pragma unroll
            for (int mi = 0; mi < 2; mi++)
#pragma unroll
                for (int ni = 0; ni < 4; ni++)
                    mma16816(c[mi][ni], aA[mi], bB[ni][0], bB[ni][1]);
        }
        // ---- stage next chunk into the other buffer; one sync per iter ----
        if (it + 1 < NIT) {
            sts_chunk(cur ^ BUF_SZ);
            __syncthreads();
        }
    }

    // ---------------- epilogue ----------------
    __syncthreads();                    // all LDSM done; reuse smem for reductions
    float* laR = reinterpret_cast<float*>(sm);            // [4][128]
    float* raR = reinterpret_cast<float*>(sm + 2048);

    const int quad = lid >> 2, tq = lid & 3;
    const float* bl  = b_lin + g * HDIM;
    const float* wal = w_al + g * HDIM;
    const float* war = w_ar + g * HDIM;

#pragma unroll
    for (int mi = 0; mi < 2; mi++)
#pragma unroll
        for (int h = 0; h < 2; h++) {
            int rl = wm * 32 + mi * 16 + h * 8 + quad;
            int rg = row0 + rl;
            bool ok = rg < N;
            float la = 0.f, ra = 0.f;
            float* dst = out_hidden + (size_t)rg * (GDIM * HDIM) + g * HDIM;
#pragma unroll
            for (int ni = 0; ni < 4; ni++) {
                int col = wn * 32 + ni * 8 + tq * 2;
                float v0 = c[mi][ni][h * 2 + 0] + __ldg(bl + col);
                float v1 = c[mi][ni][h * 2 + 1] + __ldg(bl + col + 1);
                la += v0 * __ldg(wal + col) + v1 * __ldg(wal + col + 1);
                ra += v0 * __ldg(war + col) + v1 * __ldg(war + col + 1);
                if (ok) *reinterpret_cast<float2*>(dst + col) = make_float2(v0, v1);
            }
            la += __shfl_xor_sync(0xffffffffu, la, 1);
            la += __shfl_xor_sync(0xffffffffu, la, 2);
            ra += __shfl_xor_sync(0xffffffffu, ra, 1);
            ra += __shfl_xor_sync(0xffffffffu, ra, 2);
            if (tq == 0) { laR[wn * 128 + rl] = la; raR[wn * 128 + rl] = ra; }
        }
    __syncthreads();
    if (tid < 128) {
        int rg = row0 + tid;
        if (rg < N) {
            float la = laR[tid] + laR[128 + tid] + laR[256 + tid] + laR[384 + tid];
            float ra = raR[tid] + raR[128 + tid] + raR[256 + tid] + raR[384 + tid];
            reinterpret_cast<float*>(g_al)[rg * 4 + g] = la + b_al[g];
            reinterpret_cast<float*>(g_ar)[rg * 4 + g] = ra + b_ar[g];
        }
    }
}

// ---------------- edge factors ----------------
__global__ void edge_kernel(const int* __restrict__ src,
                            const int* __restrict__ dst,
                            float* __restrict__ factors, int E, int N) {
    size_t stride = (size_t)gridDim.x * blockDim.x;
    for (size_t e = (size_t)blockIdx.x * blockDim.x + threadIdx.x; e < (size_t)E; e += stride) {
        int s = src[e]; s = s < 0 ? 0 : (s >= N ? N - 1 : s);
        int d = dst[e]; d = d < 0 ? 0 : (d >= N ? N - 1 : d);
        float4 l = g_al[s];
        float4 r = g_ar[d];
        factors[e]                 = 1.f / (1.f + __expf(-(l.x + r.x)));
        factors[(size_t)E + e]     = 1.f / (1.f + __expf(-(l.y + r.y)));
        factors[(size_t)2 * E + e] = 1.f / (1.f + __expf(-(l.z + r.z)));
        factors[(size_t)3 * E + e] = 1.f / (1.f + __expf(-(l.w + r.w)));
    }
}

// ---------------- launch ----------------
extern "C" void kernel_launch(void* const* d_in, const int* in_sizes, int n_in,
                              void* d_out, int out_size) {
    const float* feat  = (const float*)d_in[0];
    const int*   src   = (const int*)d_in[1];
    const int*   dst   = (const int*)d_in[2];
    const float* att   = (const float*)d_in[3];
    const float* Wlin  = (const float*)d_in[4];
    const float* b_lin = (const float*)d_in[5];
    const float* w_al  = (const float*)d_in[6];
    const float* b_al  = (const float*)d_in[7];
    const float* w_ar  = (const float*)d_in[8];
    const float* b_ar  = (const float*)d_in[9];

    int N = in_sizes[0] / D_IN;
    int E = in_sizes[1];
    float* out     = (float*)d_out;
    float* factors = out + (size_t)N * (GDIM * HDIM);

    cudaFuncSetAttribute(gemm_kernel, cudaFuncAttributeMaxDynamicSharedMemorySize, SM_SZ);

    prep_kernel<<<(GDIM * D_IN * HDIM + 255) / 256, 256>>>(att, Wlin);

    dim3 grid(GDIM, (N + BM - 1) / BM);   // g fastest: 4 CTAs share each feat tile via L2
    gemm_kernel<<<grid, 512, SM_SZ>>>(feat, b_lin, w_al, b_al, w_ar, b_ar, out, N);

    edge_kernel<<<2048, 256>>>(src, dst, factors, E, N);
}